// round 8
// baseline (speedup 1.0000x reference)
#include <cuda_runtime.h>
#include <cuda_bf16.h>
#include <cstdint>

// Device-global scratch (no allocations). Zero-init; last block resets.
__device__ double        g_acc       = 0.0;
__device__ unsigned int  g_acc_count = 0;

#define LOG2E 1.44269504088896340736f
#define LN2   0.69314718055994530942f

#define TILE        1024                 // groups per tile (4 rows each)
#define NSTAGE      3
#define LBYTES      (TILE * 48)          // 49152 B logits per tile
#define TBYTES      (TILE * 16)          // 16384 B targets per tile
#define STAGE_BYTES (LBYTES + TBYTES)    // 65536 B per stage

__device__ __forceinline__ float rcp_approx(float x) {
    float r; asm("rcp.approx.f32 %0, %1;" : "=f"(r) : "f"(x)); return r;
}
__device__ __forceinline__ float ex2_approx(float x) {
    float r; asm("ex2.approx.f32 %0, %1;" : "=f"(r) : "f"(x)); return r;
}
__device__ __forceinline__ float lg2_approx(float x) {
    float r; asm("lg2.approx.f32 %0, %1;" : "=f"(r) : "f"(x)); return r;
}
__device__ __forceinline__ uint32_t smem_u32(const void* p) {
    uint32_t a;
    asm("{ .reg .u64 t; cvta.to.shared.u64 t, %1; cvt.u32.u64 %0, t; }"
        : "=r"(a) : "l"(p));
    return a;
}
__device__ __forceinline__ void mbar_init(uint32_t mb, uint32_t count) {
    asm volatile("mbarrier.init.shared.b64 [%0], %1;" :: "r"(mb), "r"(count) : "memory");
}
__device__ __forceinline__ void mbar_wait(uint32_t mb, uint32_t phase) {
    uint32_t done;
    asm volatile(
        "{\n\t.reg .pred p;\n\t"
        "mbarrier.try_wait.parity.acquire.cta.shared::cta.b64 p, [%1], %2;\n\t"
        "selp.b32 %0, 1, 0, p;\n\t}"
        : "=r"(done) : "r"(mb), "r"(phase) : "memory");
    while (!done) {
        asm volatile(
            "{\n\t.reg .pred p;\n\t"
            "mbarrier.try_wait.parity.acquire.cta.shared::cta.b64 p, [%1], %2, 0x989680;\n\t"
            "selp.b32 %0, 1, 0, p;\n\t}"
            : "=r"(done) : "r"(mb), "r"(phase) : "memory");
    }
}

// Issue async bulk copies of tile t into stage `slot`. Thread 0 only.
__device__ __forceinline__ void issue_tile(uint32_t dbase, uint32_t mbase, int slot,
                                           const float* __restrict__ logits,
                                           const int*   __restrict__ targets,
                                           int t, int ngroups)
{
    const int cnt = min(TILE, ngroups - t * TILE);
    const uint32_t lb = (uint32_t)cnt * 48u;
    const uint32_t tb = (uint32_t)cnt * 16u;
    const uint32_t lsm = dbase + (uint32_t)slot * STAGE_BYTES;
    const uint32_t tsm = lsm + LBYTES;
    const uint32_t mb  = mbase + (uint32_t)slot * 8u;

    asm volatile("mbarrier.arrive.expect_tx.shared.b64 _, [%0], %1;"
                 :: "r"(mb), "r"(lb + tb) : "memory");
    const char* lsrc = (const char*)logits  + (size_t)t * LBYTES;
    const char* tsrc = (const char*)targets + (size_t)t * TBYTES;
    asm volatile("cp.async.bulk.shared::cluster.global.mbarrier::complete_tx::bytes "
                 "[%0], [%1], %2, [%3];"
                 :: "r"(lsm), "l"(lsrc), "r"(lb), "r"(mb) : "memory");
    asm volatile("cp.async.bulk.shared::cluster.global.mbarrier::complete_tx::bytes "
                 "[%0], [%1], %2, [%3];"
                 :: "r"(tsm), "l"(tsrc), "r"(tb), "r"(mb) : "memory");
}

// tbl[p*3+t] = { 1.5*P[p][t],  0.1*(p!=t),  class_w[t]*ln2,  0 }
__device__ __forceinline__ void row_loss(float l0, float l1, float l2, int t,
                                         const float4* __restrict__ tbl,
                                         float& acc)
{
    const bool  pa  = (l1 > l0);
    const float m01 = fmaxf(l0, l1);
    const bool  pb  = (l2 > m01);
    const float m   = fmaxf(m01, l2);

    const int p3  = pb ? 6 : (pa ? 3 : 0);
    const float4 e = tbl[p3 + t];

    const float nmK = -m * LOG2E;
    const float s0 = fmaf(l0, LOG2E, nmK);
    const float s1 = fmaf(l1, LOG2E, nmK);
    const float s2 = fmaf(l2, LOG2E, nmK);

    const float e0 = ex2_approx(s0);
    const float e1 = ex2_approx(s1);
    const float e2 = ex2_approx(s2);
    const float S    = e0 + e1 + e2;
    const float rcpS = rcp_approx(S);          // == max prob
    const float lg2S = lg2_approx(S);

    const float st = (t == 0) ? s0 : ((t == 1) ? s1 : s2);
    const float et = (t == 0) ? e0 : ((t == 1) ? e1 : e2);

    const float omp = fmaf(-et, rcpS, 1.0f);   // 1 - prob[target]
    const float ce2 = lg2S - st;               // ce / ln2

    acc = fmaf((e.z * omp) * omp, ce2, acc);   // focal term
    acc += e.x;                                // 1.5 * penalty
    acc = fmaf(e.y, rcpS, acc);                // 0.1 * (p!=t) * max_prob
}

__global__ void __launch_bounds__(1024, 1)
trading_loss_kernel(const float* __restrict__ logits,
                    const int*   __restrict__ targets,
                    const float* __restrict__ class_w,
                    float*       __restrict__ out,
                    int ngroups, float inv_n)
{
    extern __shared__ char dsm[];
    __shared__ uint64_t mbar[NSTAGE];
    __shared__ float4   tbl[9];
    __shared__ float    warp_sums[32];
    __shared__ bool     is_last;

    const int tid = threadIdx.x;
    const uint32_t dbase = smem_u32(dsm);
    const uint32_t mbase = smem_u32(mbar);

    if (tid < 9) {
        const int p = tid / 3;
        const int t = tid - p * 3;
        int d = p - t; d = (d < 0) ? -d : d;
        const float pen15 = 0.75f * (float)d + ((d == 2) ? 0.75f : 0.0f);
        const float confw = (d != 0) ? 0.1f : 0.0f;
        tbl[tid] = make_float4(pen15, confw, class_w[t] * LN2, 0.0f);
    }
    if (tid == 0) {
        #pragma unroll
        for (int s = 0; s < NSTAGE; ++s) mbar_init(mbase + s * 8u, 1u);
    }
    __syncthreads();

    const int ntiles = (ngroups + TILE - 1) / TILE;

    // prologue: fill stages 0..NSTAGE-2
    if (tid == 0) {
        #pragma unroll
        for (int k = 0; k < NSTAGE - 1; ++k) {
            const int t = blockIdx.x + k * gridDim.x;
            if (t < ntiles) issue_tile(dbase, mbase, k, logits, targets, t, ngroups);
        }
    }

    float acc = 0.0f;
    int slot = 0, phase = 0;

    for (int t = blockIdx.x; t < ntiles; t += gridDim.x) {
        mbar_wait(mbase + (uint32_t)slot * 8u, (uint32_t)phase);

        const int cnt = min(TILE, ngroups - t * TILE);
        const char* sl = dsm + (size_t)slot * STAGE_BYTES;

        if (tid < cnt) {
            const float4* lp = reinterpret_cast<const float4*>(sl) + (size_t)tid * 3;
            const float4 a0 = lp[0];
            const float4 a1 = lp[1];
            const float4 a2 = lp[2];
            const int4   t4 = reinterpret_cast<const int4*>(sl + LBYTES)[tid];

            row_loss(a0.x, a0.y, a0.z, t4.x, tbl, acc);
            row_loss(a0.w, a1.x, a1.y, t4.y, tbl, acc);
            row_loss(a1.z, a1.w, a2.x, t4.z, tbl, acc);
            row_loss(a2.y, a2.z, a2.w, t4.w, tbl, acc);
        }
        __syncthreads();   // all threads done with this stage before refill

        const int nt = t + (NSTAGE - 1) * gridDim.x;
        if (tid == 0 && nt < ntiles) {
            const int islot = (slot == 0) ? (NSTAGE - 1) : (slot - 1);
            issue_tile(dbase, mbase, islot, logits, targets, nt, ngroups);
        }

        if (++slot == NSTAGE) { slot = 0; phase ^= 1; }
    }

    // ---- block reduction (32 warps) ----
    #pragma unroll
    for (int off = 16; off > 0; off >>= 1)
        acc += __shfl_xor_sync(0xFFFFFFFFu, acc, off);

    const int lane = tid & 31;
    const int wid  = tid >> 5;
    if (lane == 0) warp_sums[wid] = acc;
    __syncthreads();

    if (wid == 0) {
        float v = warp_sums[lane];
        #pragma unroll
        for (int off = 16; off > 0; off >>= 1)
            v += __shfl_xor_sync(0xFFFFFFFFu, v, off);
        if (lane == 0) {
            atomicAdd(&g_acc, (double)v);
            __threadfence();
            unsigned int ticket = atomicAdd(&g_acc_count, 1u);
            is_last = (ticket == gridDim.x - 1u);
        }
    }
    __syncthreads();

    if (is_last && tid == 0) {
        double total = g_acc;
        out[0] = (float)(total * (double)inv_n);
        g_acc = 0.0;
        g_acc_count = 0u;
    }
}

extern "C" void kernel_launch(void* const* d_in, const int* in_sizes, int n_in,
                              void* d_out, int out_size)
{
    const float* logits  = (const float*)d_in[0];
    const int*   targets = (const int*)d_in[1];
    const float* class_w = (const float*)d_in[2];
    float*       out     = (float*)d_out;

    const int batch   = in_sizes[1];       // targets element count = B
    const int ngroups = batch / 4;         // 4 rows per float4-group
    const int ntiles  = (ngroups + TILE - 1) / TILE;

    int blocks = 152;                      // one block per SM (GB300: 152 SMs)
    if (blocks > ntiles) blocks = ntiles;
    if (blocks < 1) blocks = 1;

    static int attr_set = -1;              // config cache only (not a work guard)
    if (attr_set != 1) {
        cudaFuncSetAttribute(trading_loss_kernel,
                             cudaFuncAttributeMaxDynamicSharedMemorySize,
                             NSTAGE * STAGE_BYTES);
        attr_set = 1;
    }

    trading_loss_kernel<<<blocks, 1024, NSTAGE * STAGE_BYTES>>>(
        logits, targets, class_w, out, ngroups, 1.0f / (float)batch);
}

// round 9
// speedup vs baseline: 1.0780x; 1.0780x over previous
#include <cuda_runtime.h>
#include <cuda_bf16.h>
#include <cstdint>

// Device-global scratch (no allocations). Zero-init; last block resets.
__device__ double        g_acc       = 0.0;
__device__ unsigned int  g_acc_count = 0;

#define LOG2E 1.44269504088896340736f
#define LN2   0.69314718055994530942f

#define TILE        512                  // groups per tile (4 rows each)
#define NSTAGE      3
#define LBYTES      (TILE * 48)          // 24576 B logits per tile
#define TBYTES      (TILE * 16)          // 8192 B targets per tile
#define STAGE_BYTES (LBYTES + TBYTES)    // 32768 B per stage

__device__ __forceinline__ float rcp_approx(float x) {
    float r; asm("rcp.approx.f32 %0, %1;" : "=f"(r) : "f"(x)); return r;
}
__device__ __forceinline__ float ex2_approx(float x) {
    float r; asm("ex2.approx.f32 %0, %1;" : "=f"(r) : "f"(x)); return r;
}
__device__ __forceinline__ float lg2_approx(float x) {
    float r; asm("lg2.approx.f32 %0, %1;" : "=f"(r) : "f"(x)); return r;
}
__device__ __forceinline__ uint32_t smem_u32(const void* p) {
    uint32_t a;
    asm("{ .reg .u64 t; cvta.to.shared.u64 t, %1; cvt.u32.u64 %0, t; }"
        : "=r"(a) : "l"(p));
    return a;
}
__device__ __forceinline__ void mbar_init(uint32_t mb, uint32_t count) {
    asm volatile("mbarrier.init.shared.b64 [%0], %1;" :: "r"(mb), "r"(count) : "memory");
}
__device__ __forceinline__ void mbar_wait(uint32_t mb, uint32_t phase) {
    uint32_t done;
    asm volatile(
        "{\n\t.reg .pred p;\n\t"
        "mbarrier.try_wait.parity.acquire.cta.shared::cta.b64 p, [%1], %2;\n\t"
        "selp.b32 %0, 1, 0, p;\n\t}"
        : "=r"(done) : "r"(mb), "r"(phase) : "memory");
    while (!done) {
        asm volatile(
            "{\n\t.reg .pred p;\n\t"
            "mbarrier.try_wait.parity.acquire.cta.shared::cta.b64 p, [%1], %2, 0x989680;\n\t"
            "selp.b32 %0, 1, 0, p;\n\t}"
            : "=r"(done) : "r"(mb), "r"(phase) : "memory");
    }
}

// Issue async bulk copies of tile t into stage `slot`. One thread only.
__device__ __forceinline__ void issue_tile(uint32_t dbase, uint32_t mbase, int slot,
                                           const float* __restrict__ logits,
                                           const int*   __restrict__ targets,
                                           int t, int ngroups)
{
    const int cnt = min(TILE, ngroups - t * TILE);
    const uint32_t lb = (uint32_t)cnt * 48u;
    const uint32_t tb = (uint32_t)cnt * 16u;
    const uint32_t lsm = dbase + (uint32_t)slot * STAGE_BYTES;
    const uint32_t tsm = lsm + LBYTES;
    const uint32_t mb  = mbase + (uint32_t)slot * 8u;

    asm volatile("mbarrier.arrive.expect_tx.shared.b64 _, [%0], %1;"
                 :: "r"(mb), "r"(lb + tb) : "memory");
    const char* lsrc = (const char*)logits  + (size_t)t * LBYTES;
    const char* tsrc = (const char*)targets + (size_t)t * TBYTES;
    asm volatile("cp.async.bulk.shared::cluster.global.mbarrier::complete_tx::bytes "
                 "[%0], [%1], %2, [%3];"
                 :: "r"(lsm), "l"(lsrc), "r"(lb), "r"(mb) : "memory");
    asm volatile("cp.async.bulk.shared::cluster.global.mbarrier::complete_tx::bytes "
                 "[%0], [%1], %2, [%3];"
                 :: "r"(tsm), "l"(tsrc), "r"(tb), "r"(mb) : "memory");
}

// tbl[p*3+t] = { 1.5*P[p][t],  0.1*(p!=t),  class_w[t]*ln2,  0 }
__device__ __forceinline__ void row_loss(float l0, float l1, float l2, int t,
                                         const float4* __restrict__ tbl,
                                         float& acc, float& accP)
{
    const bool  pa  = (l1 > l0);
    const float m01 = fmaxf(l0, l1);
    const bool  pb  = (l2 > m01);
    const float m   = fmaxf(m01, l2);

    const int p3  = pb ? 6 : (pa ? 3 : 0);
    const float4 e = tbl[p3 + t];

    const float nmK = -m * LOG2E;
    const float s0 = fmaf(l0, LOG2E, nmK);
    const float s1 = fmaf(l1, LOG2E, nmK);
    const float s2 = fmaf(l2, LOG2E, nmK);

    const float e0 = ex2_approx(s0);
    const float e1 = ex2_approx(s1);
    const float e2 = ex2_approx(s2);
    const float S    = e0 + e1 + e2;
    const float rcpS = rcp_approx(S);          // == max prob (exp at argmax is 1)
    const float lg2S = lg2_approx(S);

    const float st = (t == 0) ? s0 : ((t == 1) ? s1 : s2);
    const float et = (t == 0) ? e0 : ((t == 1) ? e1 : e2);

    const float omp = fmaf(-et, rcpS, 1.0f);   // 1 - prob[target]
    const float ce2 = lg2S - st;               // ce / ln2

    acc  = fmaf((e.z * omp) * omp, ce2, acc);  // focal
    acc  = fmaf(e.y, rcpS, acc);               // 0.1*(p!=t)*max_prob
    accP += e.x;                               // 1.5 * penalty
}

__global__ void __launch_bounds__(512, 2)
trading_loss_kernel(const float* __restrict__ logits,
                    const int*   __restrict__ targets,
                    const float* __restrict__ class_w,
                    float*       __restrict__ out,
                    int ngroups, float inv_n)
{
    extern __shared__ char dsm[];
    __shared__ uint64_t mbar[NSTAGE];
    __shared__ float4   tbl[9];
    __shared__ float    warp_sums[16];
    __shared__ bool     is_last;

    const int tid = threadIdx.x;
    const uint32_t dbase = smem_u32(dsm);
    const uint32_t mbase = smem_u32(mbar);

    if (tid < 9) {
        const int p = tid / 3;
        const int t = tid - p * 3;
        int d = p - t; d = (d < 0) ? -d : d;
        const float pen15 = 0.75f * (float)d + ((d == 2) ? 0.75f : 0.0f);
        const float confw = (d != 0) ? 0.1f : 0.0f;
        tbl[tid] = make_float4(pen15, confw, class_w[t] * LN2, 0.0f);
    }
    if (tid == 0) {
        #pragma unroll
        for (int s = 0; s < NSTAGE; ++s) mbar_init(mbase + s * 8u, 1u);
    }
    __syncthreads();

    const int ntiles = (ngroups + TILE - 1) / TILE;

    // prologue: fill stages 0..NSTAGE-2
    if (tid == 0) {
        #pragma unroll
        for (int k = 0; k < NSTAGE - 1; ++k) {
            const int t = blockIdx.x + k * gridDim.x;
            if (t < ntiles) issue_tile(dbase, mbase, k, logits, targets, t, ngroups);
        }
    }

    float acc0 = 0.0f, acc1 = 0.0f, acc2 = 0.0f, acc3 = 0.0f, accP = 0.0f;
    int slot = 0, phase = 0;

    for (int t = blockIdx.x; t < ntiles; t += gridDim.x) {
        mbar_wait(mbase + (uint32_t)slot * 8u, (uint32_t)phase);

        const int cnt = min(TILE, ngroups - t * TILE);
        const char* sl = dsm + (size_t)slot * STAGE_BYTES;

        if (tid < cnt) {
            const float4* lp = reinterpret_cast<const float4*>(sl) + (size_t)tid * 3;
            const float4 a0 = lp[0];
            const float4 a1 = lp[1];
            const float4 a2 = lp[2];
            const int4   t4 = reinterpret_cast<const int4*>(sl + LBYTES)[tid];

            row_loss(a0.x, a0.y, a0.z, t4.x, tbl, acc0, accP);
            row_loss(a0.w, a1.x, a1.y, t4.y, tbl, acc1, accP);
            row_loss(a1.z, a1.w, a2.x, t4.z, tbl, acc2, accP);
            row_loss(a2.y, a2.z, a2.w, t4.w, tbl, acc3, accP);
        }
        __syncthreads();   // all threads done with this stage before refill

        const int nt = t + (NSTAGE - 1) * gridDim.x;
        if (tid == 0 && nt < ntiles) {
            const int islot = (slot == 0) ? (NSTAGE - 1) : (slot - 1);
            issue_tile(dbase, mbase, islot, logits, targets, nt, ngroups);
        }

        if (++slot == NSTAGE) { slot = 0; phase ^= 1; }
    }

    float acc = ((acc0 + acc1) + (acc2 + acc3)) + accP;

    // ---- block reduction (16 warps) ----
    #pragma unroll
    for (int off = 16; off > 0; off >>= 1)
        acc += __shfl_xor_sync(0xFFFFFFFFu, acc, off);

    const int lane = tid & 31;
    const int wid  = tid >> 5;
    if (lane == 0) warp_sums[wid] = acc;
    __syncthreads();

    if (wid == 0) {
        float v = (lane < 16) ? warp_sums[lane] : 0.0f;
        #pragma unroll
        for (int off = 8; off > 0; off >>= 1)
            v += __shfl_xor_sync(0xFFFFFFFFu, v, off);
        if (lane == 0) {
            atomicAdd(&g_acc, (double)v);
            __threadfence();
            unsigned int ticket = atomicAdd(&g_acc_count, 1u);
            is_last = (ticket == gridDim.x - 1u);
        }
    }
    __syncthreads();

    if (is_last && tid == 0) {
        double total = g_acc;
        out[0] = (float)(total * (double)inv_n);
        g_acc = 0.0;
        g_acc_count = 0u;
    }
}

extern "C" void kernel_launch(void* const* d_in, const int* in_sizes, int n_in,
                              void* d_out, int out_size)
{
    const float* logits  = (const float*)d_in[0];
    const int*   targets = (const int*)d_in[1];
    const float* class_w = (const float*)d_in[2];
    float*       out     = (float*)d_out;

    const int batch   = in_sizes[1];       // targets element count = B
    const int ngroups = batch / 4;         // 4 rows per float4-group
    const int ntiles  = (ngroups + TILE - 1) / TILE;

    int blocks = 152 * 2;                  // 2 blocks/SM (GB300: 152 SMs)
    if (blocks > ntiles) blocks = ntiles;
    if (blocks < 1) blocks = 1;

    cudaFuncSetAttribute(trading_loss_kernel,
                         cudaFuncAttributeMaxDynamicSharedMemorySize,
                         NSTAGE * STAGE_BYTES);

    trading_loss_kernel<<<blocks, 512, NSTAGE * STAGE_BYTES>>>(
        logits, targets, class_w, out, ngroups, 1.0f / (float)batch);
}